// round 7
// baseline (speedup 1.0000x reference)
#include <cuda_runtime.h>

#define NN 50000
#define NE 800000
#define NG 256
#define IND 128
#define HID 64
#define EMB 128

// ---------------- scratch (device globals; no allocation) ----------------
__device__ int g_src[NE];
__device__ int g_dst[NE];
__device__ int g_batch[NN];
__device__ int g_is64_edge;
__device__ int g_is64_batch;

__device__ float g_deg[NN];
__device__ float g_dis[NN];
__device__ alignas(16) float g_h1[(size_t)NN * HID];   // x @ W1
__device__ alignas(16) float g_a1[(size_t)NN * HID];   // aggregated layer 1 (pre-bias)
__device__ alignas(16) float g_h2[(size_t)NN * EMB];   // relu(a1+b1) @ W2
__device__ alignas(16) float g_a2[(size_t)NN * EMB];   // aggregated layer 2 (pre-bias)
__device__ alignas(16) float g_pool[NG * EMB];
__device__ float g_cnt[NG];

// vector f32 reduction (sm_90+): 4x fewer RED ops than scalar atomicAdd
__device__ __forceinline__ void red_add_v4(float* p, float a, float b, float c, float d) {
    asm volatile("red.global.add.v4.f32 [%0], {%1,%2,%3,%4};"
                 :: "l"(p), "f"(a), "f"(b), "f"(c), "f"(d) : "memory");
}

// ---------------- dtype probe + index conversion ----------------
// int64 data with values < 2^31: every odd 32-bit word is 0.
// int32 data: odd words are real values; edge indices are uniform in [0,50000)
// (P(all 1024 zero) ~ 0), sorted batch reaches graph>=1 within first ~400 nodes.
__global__ void k_detect(const void* ei, const void* batch) {
    if (threadIdx.x == 0 && blockIdx.x == 0) {
        const int* w = (const int*)ei;
        int ok = 1;
        for (int k = 0; k < 1024; k++)
            if (w[2 * k + 1] != 0) { ok = 0; break; }
        g_is64_edge = ok;
        const int* b = (const int*)batch;
        int ok2 = 1;
        for (int k = 0; k < 1024; k++)
            if (b[2 * k + 1] != 0) { ok2 = 0; break; }
        g_is64_batch = ok2;
    }
}

__global__ void k_cvt_edge(const void* ei) {
    int e = blockIdx.x * blockDim.x + threadIdx.x;
    if (e >= NE) return;
    if (g_is64_edge) {
        const long long* p = (const long long*)ei;
        g_src[e] = (int)p[e];
        g_dst[e] = (int)p[NE + e];
    } else {
        const int* p = (const int*)ei;
        g_src[e] = p[e];
        g_dst[e] = p[NE + e];
    }
}

__global__ void k_cvt_batch(const void* batch) {
    int i = blockIdx.x * blockDim.x + threadIdx.x;
    if (i >= NN) return;
    if (g_is64_batch) {
        g_batch[i] = (int)((const long long*)batch)[i];
    } else {
        g_batch[i] = ((const int*)batch)[i];
    }
}

// ---------------- init: deg=1 (self loop), pool/cnt = 0 ----------------
__global__ void k_init() {
    int i = blockIdx.x * blockDim.x + threadIdx.x;
    if (i < NN) g_deg[i] = 1.0f;
    if (i < NG * EMB) g_pool[i] = 0.0f;
    if (i < NG) g_cnt[i] = 0.0f;
}

__global__ void k_deg(const float* __restrict__ ew) {
    int e = blockIdx.x * blockDim.x + threadIdx.x;
    if (e < NE) atomicAdd(&g_deg[g_dst[e]], ew[e]);
}

__global__ void k_dis() {
    int i = blockIdx.x * blockDim.x + threadIdx.x;
    if (i < NN) {
        float d = g_deg[i];
        g_dis[i] = d > 0.0f ? rsqrtf(d) : 0.0f;
    }
}

// ---------------- GEMM: C[node,OUT] = f(A[node,IN]) @ W[IN,OUT] ----------------
// warp-per-node; W staged in smem; x row staged via smem broadcast.
template <int IN, int OUT, bool BIASRELU>
__device__ __forceinline__ void gemm_body(const float* __restrict__ A,
                                          const float* __restrict__ W,
                                          const float* __restrict__ bias,
                                          float* __restrict__ C) {
    __shared__ float Ws[IN * OUT];
    __shared__ float bs[IN];
    __shared__ float xs[8][32];
    for (int i = threadIdx.x; i < IN * OUT; i += blockDim.x) Ws[i] = W[i];
    if (BIASRELU)
        for (int i = threadIdx.x; i < IN; i += blockDim.x) bs[i] = bias[i];
    __syncthreads();

    const int warp = threadIdx.x >> 5;
    const int lane = threadIdx.x & 31;
    constexpr int NC = OUT / 32;

    for (int node = blockIdx.x * 8 + warp; node < NN; node += gridDim.x * 8) {
        float acc[NC];
#pragma unroll
        for (int c = 0; c < NC; c++) acc[c] = 0.0f;
        const float* row = A + (size_t)node * IN;

        for (int kb = 0; kb < IN; kb += 32) {
            float xv = row[kb + lane];
            if (BIASRELU) xv = fmaxf(xv + bs[kb + lane], 0.0f);
            xs[warp][lane] = xv;
            __syncwarp();
#pragma unroll
            for (int kk = 0; kk < 32; kk++) {
                float xk = xs[warp][kk];
                const float* wr = Ws + (kb + kk) * OUT + lane;
#pragma unroll
                for (int c = 0; c < NC; c++) acc[c] = fmaf(xk, wr[32 * c], acc[c]);
            }
            __syncwarp();
        }
#pragma unroll
        for (int c = 0; c < NC; c++)
            C[(size_t)node * OUT + lane + 32 * c] = acc[c];
    }
}

__global__ void k_gemm1(const float* __restrict__ x, const float* __restrict__ W1) {
    gemm_body<IND, HID, false>(x, W1, nullptr, g_h1);
}
__global__ void k_gemm2(const float* __restrict__ W2, const float* __restrict__ b1) {
    gemm_body<HID, EMB, true>(g_a1, W2, b1, g_h2);
}

// ---------------- self-loop init: O[i,:] = dis[i]^2 * H[i,:] ----------------
template <int DIM>
__device__ __forceinline__ void self_body(const float* __restrict__ H, float* __restrict__ O) {
    int gid = blockIdx.x * blockDim.x + threadIdx.x;
    constexpr int G = DIM / 4;
    if (gid >= NN * G) return;
    int i = gid / G, l = gid % G;
    float s = g_dis[i];
    s *= s;
    float4 h = *(const float4*)(H + (size_t)i * DIM + 4 * l);
    float4 o = {h.x * s, h.y * s, h.z * s, h.w * s};
    *(float4*)(O + (size_t)i * DIM + 4 * l) = o;
}

__global__ void k_self1() { self_body<HID>(g_h1, g_a1); }
__global__ void k_self2() { self_body<EMB>(g_h2, g_a2); }

// ---------------- edge scatter: O[dst,:] += dis[src]*w*dis[dst] * H[src,:] ----------------
template <int DIM>
__device__ __forceinline__ void edge_body(const float* __restrict__ ew,
                                          const float* __restrict__ H,
                                          float* __restrict__ O) {
    constexpr int G = DIM / 4;  // threads per edge (one float4 each)
    int gid = blockIdx.x * blockDim.x + threadIdx.x;
    if (gid >= NE * G) return;
    int e = gid / G, l = gid % G;
    int s = g_src[e];
    int d = g_dst[e];
    float coef = g_dis[s] * ew[e] * g_dis[d];
    float4 h = *(const float4*)(H + (size_t)s * DIM + 4 * l);
    red_add_v4(O + (size_t)d * DIM + 4 * l,
               h.x * coef, h.y * coef, h.z * coef, h.w * coef);
}

__global__ void k_edge1(const float* __restrict__ ew) { edge_body<HID>(ew, g_h1, g_a1); }
__global__ void k_edge2(const float* __restrict__ ew) { edge_body<EMB>(ew, g_h2, g_a2); }

// ---------------- pooling: pool[g,:] += relu(a2[i,:]+b2), cnt[g]++ ----------------
__global__ void k_pool(const float* __restrict__ b2) {
    int gid = blockIdx.x * blockDim.x + threadIdx.x;
    if (gid >= NN * 32) return;
    int i = gid >> 5, l = gid & 31;
    int g = g_batch[i];
    float4 v = *(const float4*)(g_a2 + (size_t)i * EMB + 4 * l);
    float4 b = *(const float4*)(b2 + 4 * l);
    v.x = fmaxf(v.x + b.x, 0.0f);
    v.y = fmaxf(v.y + b.y, 0.0f);
    v.z = fmaxf(v.z + b.z, 0.0f);
    v.w = fmaxf(v.w + b.w, 0.0f);
    red_add_v4(g_pool + g * EMB + 4 * l, v.x, v.y, v.z, v.w);
}

__global__ void k_cnt() {
    int i = blockIdx.x * blockDim.x + threadIdx.x;
    if (i < NN) atomicAdd(&g_cnt[g_batch[i]], 1.0f);
}

__global__ void k_div(float* __restrict__ out) {
    int gid = blockIdx.x * blockDim.x + threadIdx.x;
    if (gid < NG * EMB) out[gid] = g_pool[gid] / fmaxf(g_cnt[gid >> 7], 1.0f);
}

// ---------------- launch ----------------
extern "C" void kernel_launch(void* const* d_in, const int* in_sizes, int n_in,
                              void* d_out, int out_size) {
    const float* x     = (const float*)d_in[0];
    const void*  ei    = d_in[1];  // [2, NE] int32 or int64 — probed on device
    const float* ew    = (const float*)d_in[2];
    const void*  batch = d_in[3];
    const float* W1    = (const float*)d_in[4];
    const float* b1    = (const float*)d_in[5];
    const float* W2    = (const float*)d_in[6];
    const float* b2    = (const float*)d_in[7];
    float*       out   = (float*)d_out;

    const int T = 256;
    k_detect<<<1, 32>>>(ei, batch);
    k_cvt_edge<<<(NE + T - 1) / T, T>>>(ei);
    k_cvt_batch<<<(NN + T - 1) / T, T>>>(batch);

    k_init<<<(NN + T - 1) / T, T>>>();
    k_deg<<<(NE + T - 1) / T, T>>>(ew);
    k_dis<<<(NN + T - 1) / T, T>>>();

    // layer 1
    k_gemm1<<<(NN + 7) / 8, T>>>(x, W1);
    k_self1<<<(NN * (HID / 4) + T - 1) / T, T>>>();
    k_edge1<<<(NE * (HID / 4) + T - 1) / T, T>>>(ew);

    // layer 2 (bias+relu fused into GEMM2 input load)
    k_gemm2<<<(NN + 7) / 8, T>>>(W2, b1);
    k_self2<<<(NN * (EMB / 4) + T - 1) / T, T>>>();
    k_edge2<<<(NE * (EMB / 4) + T - 1) / T, T>>>(ew);

    // pool (bias+relu fused) + mean
    k_pool<<<(NN * 32 + T - 1) / T, T>>>(b2);
    k_cnt<<<(NN + T - 1) / T, T>>>();
    k_div<<<(NG * EMB + T - 1) / T, T>>>(out);
}

// round 8
// speedup vs baseline: 1.0009x; 1.0009x over previous
#include <cuda_runtime.h>

#define NN 50000
#define NE 800000
#define NG 256
#define IND 128
#define HID 64
#define EMB 128

// ---------------- scratch (device globals; no allocation) ----------------
__device__ int g_src[NE];
__device__ int g_dst[NE];
__device__ int g_batch[NN];
__device__ int g_is64_edge;
__device__ int g_is64_batch;

__device__ float g_deg[NN];
__device__ float g_dis[NN];
__device__ alignas(16) float g_h1[(size_t)NN * HID];   // x @ W1
__device__ alignas(16) float g_a1[(size_t)NN * HID];   // aggregated layer 1 (pre-bias)
__device__ alignas(16) float g_h2[(size_t)NN * EMB];   // relu(a1+b1) @ W2
__device__ alignas(16) float g_a2[(size_t)NN * EMB];   // aggregated layer 2 (pre-bias)
__device__ alignas(16) float g_pool[NG * EMB];
__device__ float g_cnt[NG];

// vector f32 reduction (sm_90+): 4x fewer RED ops than scalar atomicAdd
__device__ __forceinline__ void red_add_v4(float* p, float a, float b, float c, float d) {
    asm volatile("red.global.add.v4.f32 [%0], {%1,%2,%3,%4};"
                 :: "l"(p), "f"(a), "f"(b), "f"(c), "f"(d) : "memory");
}

// ---------------- dtype probe + index conversion ----------------
// int64 data with values < 2^31: every odd 32-bit word is 0.
// int32 data: odd words are real values; edge indices are uniform in [0,50000)
// (P(all 1024 zero) ~ 0), sorted batch reaches graph>=1 within first ~400 nodes.
__global__ void k_detect(const void* ei, const void* batch) {
    if (threadIdx.x == 0 && blockIdx.x == 0) {
        const int* w = (const int*)ei;
        int ok = 1;
        for (int k = 0; k < 1024; k++)
            if (w[2 * k + 1] != 0) { ok = 0; break; }
        g_is64_edge = ok;
        const int* b = (const int*)batch;
        int ok2 = 1;
        for (int k = 0; k < 1024; k++)
            if (b[2 * k + 1] != 0) { ok2 = 0; break; }
        g_is64_batch = ok2;
    }
}

__global__ void k_cvt_edge(const void* ei) {
    int e = blockIdx.x * blockDim.x + threadIdx.x;
    if (e >= NE) return;
    if (g_is64_edge) {
        const long long* p = (const long long*)ei;
        g_src[e] = (int)p[e];
        g_dst[e] = (int)p[NE + e];
    } else {
        const int* p = (const int*)ei;
        g_src[e] = p[e];
        g_dst[e] = p[NE + e];
    }
}

__global__ void k_cvt_batch(const void* batch) {
    int i = blockIdx.x * blockDim.x + threadIdx.x;
    if (i >= NN) return;
    if (g_is64_batch) {
        g_batch[i] = (int)((const long long*)batch)[i];
    } else {
        g_batch[i] = ((const int*)batch)[i];
    }
}

// ---------------- init: deg=1 (self loop), pool/cnt = 0 ----------------
__global__ void k_init() {
    int i = blockIdx.x * blockDim.x + threadIdx.x;
    if (i < NN) g_deg[i] = 1.0f;
    if (i < NG * EMB) g_pool[i] = 0.0f;
    if (i < NG) g_cnt[i] = 0.0f;
}

__global__ void k_deg(const float* __restrict__ ew) {
    int e = blockIdx.x * blockDim.x + threadIdx.x;
    if (e < NE) atomicAdd(&g_deg[g_dst[e]], ew[e]);
}

__global__ void k_dis() {
    int i = blockIdx.x * blockDim.x + threadIdx.x;
    if (i < NN) {
        float d = g_deg[i];
        g_dis[i] = d > 0.0f ? rsqrtf(d) : 0.0f;
    }
}

// ---------------- GEMM: C[node,OUT] = f(A[node,IN]) @ W[IN,OUT] ----------------
// warp-per-node; W staged in smem; x row staged via smem broadcast.
template <int IN, int OUT, bool BIASRELU>
__device__ __forceinline__ void gemm_body(const float* __restrict__ A,
                                          const float* __restrict__ W,
                                          const float* __restrict__ bias,
                                          float* __restrict__ C) {
    __shared__ float Ws[IN * OUT];
    __shared__ float bs[IN];
    __shared__ float xs[8][32];
    for (int i = threadIdx.x; i < IN * OUT; i += blockDim.x) Ws[i] = W[i];
    if (BIASRELU)
        for (int i = threadIdx.x; i < IN; i += blockDim.x) bs[i] = bias[i];
    __syncthreads();

    const int warp = threadIdx.x >> 5;
    const int lane = threadIdx.x & 31;
    constexpr int NC = OUT / 32;

    for (int node = blockIdx.x * 8 + warp; node < NN; node += gridDim.x * 8) {
        float acc[NC];
#pragma unroll
        for (int c = 0; c < NC; c++) acc[c] = 0.0f;
        const float* row = A + (size_t)node * IN;

        for (int kb = 0; kb < IN; kb += 32) {
            float xv = row[kb + lane];
            if (BIASRELU) xv = fmaxf(xv + bs[kb + lane], 0.0f);
            xs[warp][lane] = xv;
            __syncwarp();
#pragma unroll
            for (int kk = 0; kk < 32; kk++) {
                float xk = xs[warp][kk];
                const float* wr = Ws + (kb + kk) * OUT + lane;
#pragma unroll
                for (int c = 0; c < NC; c++) acc[c] = fmaf(xk, wr[32 * c], acc[c]);
            }
            __syncwarp();
        }
#pragma unroll
        for (int c = 0; c < NC; c++)
            C[(size_t)node * OUT + lane + 32 * c] = acc[c];
    }
}

__global__ void k_gemm1(const float* __restrict__ x, const float* __restrict__ W1) {
    gemm_body<IND, HID, false>(x, W1, nullptr, g_h1);
}
__global__ void k_gemm2(const float* __restrict__ W2, const float* __restrict__ b1) {
    gemm_body<HID, EMB, true>(g_a1, W2, b1, g_h2);
}

// ---------------- self-loop init: O[i,:] = dis[i]^2 * H[i,:] ----------------
template <int DIM>
__device__ __forceinline__ void self_body(const float* __restrict__ H, float* __restrict__ O) {
    int gid = blockIdx.x * blockDim.x + threadIdx.x;
    constexpr int G = DIM / 4;
    if (gid >= NN * G) return;
    int i = gid / G, l = gid % G;
    float s = g_dis[i];
    s *= s;
    float4 h = *(const float4*)(H + (size_t)i * DIM + 4 * l);
    float4 o = {h.x * s, h.y * s, h.z * s, h.w * s};
    *(float4*)(O + (size_t)i * DIM + 4 * l) = o;
}

__global__ void k_self1() { self_body<HID>(g_h1, g_a1); }
__global__ void k_self2() { self_body<EMB>(g_h2, g_a2); }

// ---------------- edge scatter: O[dst,:] += dis[src]*w*dis[dst] * H[src,:] ----------------
template <int DIM>
__device__ __forceinline__ void edge_body(const float* __restrict__ ew,
                                          const float* __restrict__ H,
                                          float* __restrict__ O) {
    constexpr int G = DIM / 4;  // threads per edge (one float4 each)
    int gid = blockIdx.x * blockDim.x + threadIdx.x;
    if (gid >= NE * G) return;
    int e = gid / G, l = gid % G;
    int s = g_src[e];
    int d = g_dst[e];
    float coef = g_dis[s] * ew[e] * g_dis[d];
    float4 h = *(const float4*)(H + (size_t)s * DIM + 4 * l);
    red_add_v4(O + (size_t)d * DIM + 4 * l,
               h.x * coef, h.y * coef, h.z * coef, h.w * coef);
}

__global__ void k_edge1(const float* __restrict__ ew) { edge_body<HID>(ew, g_h1, g_a1); }
__global__ void k_edge2(const float* __restrict__ ew) { edge_body<EMB>(ew, g_h2, g_a2); }

// ---------------- pooling: pool[g,:] += relu(a2[i,:]+b2), cnt[g]++ ----------------
__global__ void k_pool(const float* __restrict__ b2) {
    int gid = blockIdx.x * blockDim.x + threadIdx.x;
    if (gid >= NN * 32) return;
    int i = gid >> 5, l = gid & 31;
    int g = g_batch[i];
    float4 v = *(const float4*)(g_a2 + (size_t)i * EMB + 4 * l);
    float4 b = *(const float4*)(b2 + 4 * l);
    v.x = fmaxf(v.x + b.x, 0.0f);
    v.y = fmaxf(v.y + b.y, 0.0f);
    v.z = fmaxf(v.z + b.z, 0.0f);
    v.w = fmaxf(v.w + b.w, 0.0f);
    red_add_v4(g_pool + g * EMB + 4 * l, v.x, v.y, v.z, v.w);
}

__global__ void k_cnt() {
    int i = blockIdx.x * blockDim.x + threadIdx.x;
    if (i < NN) atomicAdd(&g_cnt[g_batch[i]], 1.0f);
}

__global__ void k_div(float* __restrict__ out) {
    int gid = blockIdx.x * blockDim.x + threadIdx.x;
    if (gid < NG * EMB) out[gid] = g_pool[gid] / fmaxf(g_cnt[gid >> 7], 1.0f);
}

// ---------------- launch ----------------
extern "C" void kernel_launch(void* const* d_in, const int* in_sizes, int n_in,
                              void* d_out, int out_size) {
    const float* x     = (const float*)d_in[0];
    const void*  ei    = d_in[1];  // [2, NE] int32 or int64 — probed on device
    const float* ew    = (const float*)d_in[2];
    const void*  batch = d_in[3];
    const float* W1    = (const float*)d_in[4];
    const float* b1    = (const float*)d_in[5];
    const float* W2    = (const float*)d_in[6];
    const float* b2    = (const float*)d_in[7];
    float*       out   = (float*)d_out;

    const int T = 256;
    k_detect<<<1, 32>>>(ei, batch);
    k_cvt_edge<<<(NE + T - 1) / T, T>>>(ei);
    k_cvt_batch<<<(NN + T - 1) / T, T>>>(batch);

    k_init<<<(NN + T - 1) / T, T>>>();
    k_deg<<<(NE + T - 1) / T, T>>>(ew);
    k_dis<<<(NN + T - 1) / T, T>>>();

    // layer 1
    k_gemm1<<<(NN + 7) / 8, T>>>(x, W1);
    k_self1<<<(NN * (HID / 4) + T - 1) / T, T>>>();
    k_edge1<<<(NE * (HID / 4) + T - 1) / T, T>>>(ew);

    // layer 2 (bias+relu fused into GEMM2 input load)
    k_gemm2<<<(NN + 7) / 8, T>>>(W2, b1);
    k_self2<<<(NN * (EMB / 4) + T - 1) / T, T>>>();
    k_edge2<<<(NE * (EMB / 4) + T - 1) / T, T>>>(ew);

    // pool (bias+relu fused) + mean
    k_pool<<<(NN * 32 + T - 1) / T, T>>>(b2);
    k_cnt<<<(NN + T - 1) / T, T>>>();
    k_div<<<(NG * EMB + T - 1) / T, T>>>(out);
}

// round 10
// speedup vs baseline: 1.3323x; 1.3311x over previous
#include <cuda_runtime.h>

#define NN 50000
#define NE 800000
#define NG 256
#define IND 128
#define HID 64
#define EMB 128

// ---------------- scratch (device globals; no allocation) ----------------
__device__ int g_src[NE];
__device__ int g_dst[NE];
__device__ int g_batch[NN];
__device__ int g_is64_edge;
__device__ int g_is64_batch;

__device__ int g_cntn[NN];       // edge count per dst node
__device__ int g_rowptr[NN + 1]; // CSR row pointers
__device__ int g_bsum[256];      // scan block sums
__device__ int g_boff[256];      // scan block offsets
__device__ int g_cursor[NN];     // scatter cursors

__device__ int   g_es_src[NE];   // dst-sorted edge sources
__device__ float g_es_coef[NE];  // dst-sorted edge coefficients dis[s]*w*dis[d]

__device__ float g_deg[NN];
__device__ float g_dis[NN];
__device__ alignas(16) float g_h1[(size_t)NN * HID];    // x @ W1
__device__ alignas(16) float g_hr[(size_t)NN * HID];    // relu(A*h1 + b1)
__device__ alignas(16) float g_agg2[(size_t)NN * HID];  // A * hr
__device__ alignas(16) float g_h2[(size_t)NN * EMB];    // agg2 @ W2
__device__ alignas(16) float g_pool[NG * EMB];
__device__ float g_cnt[NG];

// vector f32 reduction (sm_90+)
__device__ __forceinline__ void red_add_v4(float* p, float a, float b, float c, float d) {
    asm volatile("red.global.add.v4.f32 [%0], {%1,%2,%3,%4};"
                 :: "l"(p), "f"(a), "f"(b), "f"(c), "f"(d) : "memory");
}

// ---------------- dtype probe ----------------
__global__ void k_detect(const void* ei, const void* batch) {
    if (threadIdx.x == 0 && blockIdx.x == 0) {
        const int* w = (const int*)ei;
        int ok = 1;
        for (int k = 0; k < 1024; k++)
            if (w[2 * k + 1] != 0) { ok = 0; break; }
        g_is64_edge = ok;
        const int* b = (const int*)batch;
        int ok2 = 1;
        for (int k = 0; k < 1024; k++)
            if (b[2 * k + 1] != 0) { ok2 = 0; break; }
        g_is64_batch = ok2;
    }
}

// ---------------- init: deg=1 (self loop), counters/pool = 0 ----------------
__global__ void k_init() {
    int i = blockIdx.x * blockDim.x + threadIdx.x;
    if (i < NN) {
        g_deg[i] = 1.0f;
        g_cntn[i] = 0;
    }
    if (i < NG * EMB) g_pool[i] = 0.0f;
    if (i < NG) g_cnt[i] = 0.0f;
}

// convert edges + histogram (count per dst) + weighted degree, one pass
__global__ void k_cvt_edge(const void* ei, const float* __restrict__ ew) {
    int e = blockIdx.x * blockDim.x + threadIdx.x;
    if (e >= NE) return;
    int s, d;
    if (g_is64_edge) {
        const long long* p = (const long long*)ei;
        s = (int)p[e];
        d = (int)p[NE + e];
    } else {
        const int* p = (const int*)ei;
        s = p[e];
        d = p[NE + e];
    }
    g_src[e] = s;
    g_dst[e] = d;
    atomicAdd(&g_cntn[d], 1);
    atomicAdd(&g_deg[d], ew[e]);
}

__global__ void k_cvt_batch(const void* batch) {
    int i = blockIdx.x * blockDim.x + threadIdx.x;
    if (i >= NN) return;
    if (g_is64_batch) {
        g_batch[i] = (int)((const long long*)batch)[i];
    } else {
        g_batch[i] = ((const int*)batch)[i];
    }
}

__global__ void k_dis() {
    int i = blockIdx.x * blockDim.x + threadIdx.x;
    if (i < NN) {
        float d = g_deg[i];
        g_dis[i] = d > 0.0f ? rsqrtf(d) : 0.0f;
    }
}

// ---------------- 3-pass exclusive scan of g_cntn -> g_rowptr ----------------
__global__ void k_scan1() {
    __shared__ int sm[256];
    int t = threadIdx.x;
    int i = blockIdx.x * 256 + t;
    int v = (i < NN) ? g_cntn[i] : 0;
    sm[t] = v;
    __syncthreads();
#pragma unroll
    for (int off = 1; off < 256; off <<= 1) {
        int add = (t >= off) ? sm[t - off] : 0;
        __syncthreads();
        sm[t] += add;
        __syncthreads();
    }
    if (i < NN) g_rowptr[i] = sm[t] - v;  // exclusive
    if (t == 255) g_bsum[blockIdx.x] = sm[255];
}

__global__ void k_scan2(int nblk) {
    __shared__ int sm[256];
    int t = threadIdx.x;
    int v = (t < nblk) ? g_bsum[t] : 0;
    sm[t] = v;
    __syncthreads();
#pragma unroll
    for (int off = 1; off < 256; off <<= 1) {
        int add = (t >= off) ? sm[t - off] : 0;
        __syncthreads();
        sm[t] += add;
        __syncthreads();
    }
    if (t < nblk) g_boff[t] = sm[t] - v;  // exclusive
    if (t == 0) g_rowptr[NN] = NE;
}

__global__ void k_scan3() {
    int i = blockIdx.x * blockDim.x + threadIdx.x;
    if (i < NN) {
        int r = g_rowptr[i] + g_boff[i >> 8];
        g_rowptr[i] = r;
        g_cursor[i] = r;
    }
}

// scatter edges into dst-sorted order with precomputed coefficient
__global__ void k_scatter(const float* __restrict__ ew) {
    int e = blockIdx.x * blockDim.x + threadIdx.x;
    if (e >= NE) return;
    int s = g_src[e];
    int d = g_dst[e];
    int pos = atomicAdd(&g_cursor[d], 1);
    g_es_src[pos] = s;
    g_es_coef[pos] = g_dis[s] * ew[e] * g_dis[d];
}

// ---------------- GEMM: C[node,OUT] = A[node,IN] @ W[IN,OUT] ----------------
template <int IN, int OUT>
__device__ __forceinline__ void gemm_body(const float* __restrict__ A,
                                          const float* __restrict__ W,
                                          float* __restrict__ C) {
    __shared__ float Ws[IN * OUT];
    __shared__ float xs[8][32];
    for (int i = threadIdx.x; i < IN * OUT; i += blockDim.x) Ws[i] = W[i];
    __syncthreads();

    const int warp = threadIdx.x >> 5;
    const int lane = threadIdx.x & 31;
    constexpr int NC = OUT / 32;

    for (int node = blockIdx.x * 8 + warp; node < NN; node += gridDim.x * 8) {
        float acc[NC];
#pragma unroll
        for (int c = 0; c < NC; c++) acc[c] = 0.0f;
        const float* row = A + (size_t)node * IN;

        for (int kb = 0; kb < IN; kb += 32) {
            xs[warp][lane] = row[kb + lane];
            __syncwarp();
#pragma unroll
            for (int kk = 0; kk < 32; kk++) {
                float xk = xs[warp][kk];
                const float* wr = Ws + (kb + kk) * OUT + lane;
#pragma unroll
                for (int c = 0; c < NC; c++) acc[c] = fmaf(xk, wr[32 * c], acc[c]);
            }
            __syncwarp();
        }
#pragma unroll
        for (int c = 0; c < NC; c++)
            C[(size_t)node * OUT + lane + 32 * c] = acc[c];
    }
}

__global__ void k_gemm1(const float* __restrict__ x, const float* __restrict__ W1) {
    gemm_body<IND, HID>(x, W1, g_h1);
}
__global__ void k_gemm2(const float* __restrict__ W2) {
    gemm_body<HID, EMB>(g_agg2, W2, g_h2);
}

// ---------------- CSR aggregation over 64-dim rows, warp per dst node -------
// O[i,:] = f( dis[i]^2 * H[i,:] + sum_e coef[e]*H[src[e],:] )
// f = relu(.+bias) when RELU, identity otherwise.
// NOTE: H and O are selected INSIDE device code (never pass __device__ symbols
// from host — host-side shadow address + ATS silently reads host memory).
template <bool RELU>
__device__ __forceinline__ void agg_body(const float* __restrict__ H,
                                         const float* __restrict__ bias,
                                         float* __restrict__ O) {
    int node = (blockIdx.x * blockDim.x + threadIdx.x) >> 5;
    int lane = threadIdx.x & 31;
    if (node >= NN) return;

    const float2* __restrict__ H2 = (const float2*)H;
    int start = g_rowptr[node];
    int end = g_rowptr[node + 1];

    float s = g_dis[node];
    s *= s;
    float2 h = H2[(size_t)node * 32 + lane];
    float2 acc = {s * h.x, s * h.y};

    int k = start;
    int n4 = start + ((end - start) & ~3);
    for (; k < n4; k += 4) {
        int s0 = g_es_src[k], s1 = g_es_src[k + 1];
        int s2 = g_es_src[k + 2], s3 = g_es_src[k + 3];
        float c0 = g_es_coef[k], c1 = g_es_coef[k + 1];
        float c2 = g_es_coef[k + 2], c3 = g_es_coef[k + 3];
        float2 h0 = H2[(size_t)s0 * 32 + lane];
        float2 h1 = H2[(size_t)s1 * 32 + lane];
        float2 h2 = H2[(size_t)s2 * 32 + lane];
        float2 h3 = H2[(size_t)s3 * 32 + lane];
        acc.x = fmaf(c0, h0.x, acc.x); acc.y = fmaf(c0, h0.y, acc.y);
        acc.x = fmaf(c1, h1.x, acc.x); acc.y = fmaf(c1, h1.y, acc.y);
        acc.x = fmaf(c2, h2.x, acc.x); acc.y = fmaf(c2, h2.y, acc.y);
        acc.x = fmaf(c3, h3.x, acc.x); acc.y = fmaf(c3, h3.y, acc.y);
    }
    for (; k < end; k++) {
        int si = g_es_src[k];
        float c = g_es_coef[k];
        float2 hh = H2[(size_t)si * 32 + lane];
        acc.x = fmaf(c, hh.x, acc.x);
        acc.y = fmaf(c, hh.y, acc.y);
    }

    if (RELU) {
        float2 b = ((const float2*)bias)[lane];
        acc.x = fmaxf(acc.x + b.x, 0.0f);
        acc.y = fmaxf(acc.y + b.y, 0.0f);
    }
    ((float2*)O)[(size_t)node * 32 + lane] = acc;
}

__global__ void k_agg1(const float* __restrict__ b1) {
    agg_body<true>(g_h1, b1, g_hr);     // g_hr = relu(A*g_h1 + b1)
}
__global__ void k_agg2() {
    agg_body<false>(g_hr, nullptr, g_agg2);  // g_agg2 = A*g_hr
}

// ---------------- pooling: pool[g,:] += relu(h2[i,:]+b2), cnt[g]++ ----------
__global__ void k_pool(const float* __restrict__ b2) {
    int gid = blockIdx.x * blockDim.x + threadIdx.x;
    if (gid >= NN * 32) return;
    int i = gid >> 5, l = gid & 31;
    int g = g_batch[i];
    float4 v = *(const float4*)(g_h2 + (size_t)i * EMB + 4 * l);
    float4 b = *(const float4*)(b2 + 4 * l);
    v.x = fmaxf(v.x + b.x, 0.0f);
    v.y = fmaxf(v.y + b.y, 0.0f);
    v.z = fmaxf(v.z + b.z, 0.0f);
    v.w = fmaxf(v.w + b.w, 0.0f);
    red_add_v4(g_pool + g * EMB + 4 * l, v.x, v.y, v.z, v.w);
}

__global__ void k_cnt() {
    int i = blockIdx.x * blockDim.x + threadIdx.x;
    if (i < NN) atomicAdd(&g_cnt[g_batch[i]], 1.0f);
}

__global__ void k_div(float* __restrict__ out) {
    int gid = blockIdx.x * blockDim.x + threadIdx.x;
    if (gid < NG * EMB) out[gid] = g_pool[gid] / fmaxf(g_cnt[gid >> 7], 1.0f);
}

// ---------------- launch ----------------
extern "C" void kernel_launch(void* const* d_in, const int* in_sizes, int n_in,
                              void* d_out, int out_size) {
    const float* x     = (const float*)d_in[0];
    const void*  ei    = d_in[1];  // [2, NE] int32 or int64 — probed on device
    const float* ew    = (const float*)d_in[2];
    const void*  batch = d_in[3];
    const float* W1    = (const float*)d_in[4];
    const float* b1    = (const float*)d_in[5];
    const float* W2    = (const float*)d_in[6];
    const float* b2    = (const float*)d_in[7];
    float*       out   = (float*)d_out;

    const int T = 256;
    const int NBLK = (NN + 255) / 256;  // 196

    k_detect<<<1, 32>>>(ei, batch);
    k_init<<<(NN + T - 1) / T, T>>>();
    k_cvt_edge<<<(NE + T - 1) / T, T>>>(ei, ew);
    k_cvt_batch<<<(NN + T - 1) / T, T>>>(batch);

    // CSR build
    k_scan1<<<NBLK, 256>>>();
    k_scan2<<<1, 256>>>(NBLK);
    k_scan3<<<(NN + T - 1) / T, T>>>();
    k_dis<<<(NN + T - 1) / T, T>>>();
    k_scatter<<<(NE + T - 1) / T, T>>>(ew);

    // layer 1: h1 = x@W1 ; hr = relu(A*h1 + b1)
    k_gemm1<<<(NN + 7) / 8, T>>>(x, W1);
    k_agg1<<<(NN * 32 + T - 1) / T, T>>>(b1);

    // layer 2 (associativity): agg2 = A*hr ; h2 = agg2@W2  (b2+relu in pool)
    k_agg2<<<(NN * 32 + T - 1) / T, T>>>();
    k_gemm2<<<(NN + 7) / 8, T>>>(W2);

    // pool + mean
    k_pool<<<(NN * 32 + T - 1) / T, T>>>(b2);
    k_cnt<<<(NN + T - 1) / T, T>>>();
    k_div<<<(NG * EMB + T - 1) / T, T>>>(out);
}

// round 11
// speedup vs baseline: 2.1356x; 1.6029x over previous
#include <cuda_runtime.h>

#define NN 50000
#define NE 800000
#define NG 256
#define IND 128
#define HID 64
#define EMB 128

// ---------------- scratch (device globals; no allocation) ----------------
__device__ int g_src[NE];
__device__ int g_dst[NE];
__device__ int g_batch[NN];
__device__ int g_is64_edge;
__device__ int g_is64_batch;

__device__ int g_cntn[NN];       // edge count per dst node
__device__ int g_rowptr[NN + 1]; // CSR row pointers
__device__ int g_bsum[256];      // scan block sums
__device__ int g_boff[256];      // scan block offsets
__device__ int g_cursor[NN];     // scatter cursors

__device__ int   g_es_src[NE];   // dst-sorted edge sources
__device__ float g_es_coef[NE];  // dst-sorted edge coefficients dis[s]*w*dis[d]

__device__ float g_deg[NN];
__device__ float g_dis[NN];
__device__ alignas(16) float g_h1[(size_t)NN * HID];    // x @ W1
__device__ alignas(16) float g_hr[(size_t)NN * HID];    // relu(A*h1 + b1)
__device__ alignas(16) float g_agg2[(size_t)NN * HID];  // A * hr
__device__ alignas(16) float g_pool[NG * EMB];
__device__ float g_cnt[NG];

// vector f32 reduction (sm_90+)
__device__ __forceinline__ void red_add_v4(float* p, float a, float b, float c, float d) {
    asm volatile("red.global.add.v4.f32 [%0], {%1,%2,%3,%4};"
                 :: "l"(p), "f"(a), "f"(b), "f"(c), "f"(d) : "memory");
}

// ---------------- dtype probe ----------------
__global__ void k_detect(const void* ei, const void* batch) {
    if (threadIdx.x == 0 && blockIdx.x == 0) {
        const int* w = (const int*)ei;
        int ok = 1;
        for (int k = 0; k < 1024; k++)
            if (w[2 * k + 1] != 0) { ok = 0; break; }
        g_is64_edge = ok;
        const int* b = (const int*)batch;
        int ok2 = 1;
        for (int k = 0; k < 1024; k++)
            if (b[2 * k + 1] != 0) { ok2 = 0; break; }
        g_is64_batch = ok2;
    }
}

// ---------------- init: deg=1 (self loop), counters/pool = 0 ----------------
__global__ void k_init() {
    int i = blockIdx.x * blockDim.x + threadIdx.x;
    if (i < NN) {
        g_deg[i] = 1.0f;
        g_cntn[i] = 0;
    }
    if (i < NG * EMB) g_pool[i] = 0.0f;
    if (i < NG) g_cnt[i] = 0.0f;
}

// convert edges + histogram (count per dst) + weighted degree, one pass
__global__ void k_cvt_edge(const void* ei, const float* __restrict__ ew) {
    int e = blockIdx.x * blockDim.x + threadIdx.x;
    if (e >= NE) return;
    int s, d;
    if (g_is64_edge) {
        const long long* p = (const long long*)ei;
        s = (int)p[e];
        d = (int)p[NE + e];
    } else {
        const int* p = (const int*)ei;
        s = p[e];
        d = p[NE + e];
    }
    g_src[e] = s;
    g_dst[e] = d;
    atomicAdd(&g_cntn[d], 1);
    atomicAdd(&g_deg[d], ew[e]);
}

// convert batch + per-graph node count
__global__ void k_cvt_batch(const void* batch) {
    int i = blockIdx.x * blockDim.x + threadIdx.x;
    if (i >= NN) return;
    int b;
    if (g_is64_batch) b = (int)((const long long*)batch)[i];
    else              b = ((const int*)batch)[i];
    g_batch[i] = b;
    atomicAdd(&g_cnt[b], 1.0f);
}

// ---------------- 3-pass exclusive scan of g_cntn -> g_rowptr ----------------
__global__ void k_scan1() {
    __shared__ int sm[256];
    int t = threadIdx.x;
    int i = blockIdx.x * 256 + t;
    int v = (i < NN) ? g_cntn[i] : 0;
    sm[t] = v;
    __syncthreads();
#pragma unroll
    for (int off = 1; off < 256; off <<= 1) {
        int add = (t >= off) ? sm[t - off] : 0;
        __syncthreads();
        sm[t] += add;
        __syncthreads();
    }
    if (i < NN) g_rowptr[i] = sm[t] - v;  // exclusive
    if (t == 255) g_bsum[blockIdx.x] = sm[255];
}

__global__ void k_scan2(int nblk) {
    __shared__ int sm[256];
    int t = threadIdx.x;
    int v = (t < nblk) ? g_bsum[t] : 0;
    sm[t] = v;
    __syncthreads();
#pragma unroll
    for (int off = 1; off < 256; off <<= 1) {
        int add = (t >= off) ? sm[t - off] : 0;
        __syncthreads();
        sm[t] += add;
        __syncthreads();
    }
    if (t < nblk) g_boff[t] = sm[t] - v;  // exclusive
    if (t == 0) g_rowptr[NN] = NE;
}

// finalize rowptr/cursor + dis = rsqrt(deg) (fused)
__global__ void k_scan3() {
    int i = blockIdx.x * blockDim.x + threadIdx.x;
    if (i < NN) {
        int r = g_rowptr[i] + g_boff[i >> 8];
        g_rowptr[i] = r;
        g_cursor[i] = r;
        float d = g_deg[i];
        g_dis[i] = d > 0.0f ? rsqrtf(d) : 0.0f;
    }
}

// scatter edges into dst-sorted order with precomputed coefficient
__global__ void k_scatter(const float* __restrict__ ew) {
    int e = blockIdx.x * blockDim.x + threadIdx.x;
    if (e >= NE) return;
    int s = g_src[e];
    int d = g_dst[e];
    int pos = atomicAdd(&g_cursor[d], 1);
    g_es_src[pos] = s;
    g_es_coef[pos] = g_dis[s] * ew[e] * g_dis[d];
}

// ---------------- register-tiled GEMM: C[n,OUT] = A[n,IN] @ W[IN,OUT] -------
// MT=4 nodes per warp; lane owns VEC contiguous output cols (vector W loads).
// POOLFUSE: skip C entirely; epilogue does relu(acc+bias) and v4-RED into
// g_pool[g_batch[node]]. Otherwise store rows to C.
template <int IN, int OUT, bool POOLFUSE>
__device__ __forceinline__ void gemm_tiled(const float* __restrict__ A,
                                           const float* __restrict__ W,
                                           const float* __restrict__ bias,
                                           float* __restrict__ C) {
    constexpr int MT = 4;
    constexpr int VEC = OUT / 32;  // 2 (OUT=64) or 4 (OUT=128)
    __shared__ __align__(16) float Ws[IN * OUT];
    __shared__ float xs[8][MT][32];
    for (int i = threadIdx.x; i < IN * OUT; i += blockDim.x) Ws[i] = W[i];
    __syncthreads();

    const int warp = threadIdx.x >> 5;
    const int lane = threadIdx.x & 31;
    const int n0 = (blockIdx.x * 8 + warp) * MT;
    if (n0 >= NN) return;

    float acc[MT][VEC];
#pragma unroll
    for (int m = 0; m < MT; m++)
#pragma unroll
        for (int c = 0; c < VEC; c++) acc[m][c] = 0.0f;

    for (int kb = 0; kb < IN; kb += 32) {
#pragma unroll
        for (int m = 0; m < MT; m++)
            xs[warp][m][lane] = (n0 + m < NN) ? A[(size_t)(n0 + m) * IN + kb + lane] : 0.0f;
        __syncwarp();
#pragma unroll
        for (int kk = 0; kk < 32; kk++) {
            float wv[VEC];
            if (VEC == 4) {
                float4 t = *(const float4*)(Ws + (kb + kk) * OUT + 4 * lane);
                wv[0] = t.x; wv[1] = t.y; wv[2] = t.z; wv[3] = t.w;
            } else {
                float2 t = *(const float2*)(Ws + (kb + kk) * OUT + 2 * lane);
                wv[0] = t.x; wv[1] = t.y;
            }
#pragma unroll
            for (int m = 0; m < MT; m++) {
                float xm = xs[warp][m][kk];
#pragma unroll
                for (int c = 0; c < VEC; c++) acc[m][c] = fmaf(xm, wv[c], acc[m][c]);
            }
        }
        __syncwarp();
    }

    if (POOLFUSE) {
        float4 b = ((const float4*)bias)[lane];
#pragma unroll
        for (int m = 0; m < MT; m++) {
            if (n0 + m >= NN) break;
            int g = g_batch[n0 + m];
            float vx = fmaxf(acc[m][0] + b.x, 0.0f);
            float vy = fmaxf(acc[m][1] + b.y, 0.0f);
            float vz = fmaxf(acc[m][2] + b.z, 0.0f);
            float vw = fmaxf(acc[m][3] + b.w, 0.0f);
            red_add_v4(g_pool + g * EMB + 4 * lane, vx, vy, vz, vw);
        }
    } else {
#pragma unroll
        for (int m = 0; m < MT; m++) {
            if (n0 + m >= NN) break;
            if (VEC == 2) {
                float2 o = {acc[m][0], acc[m][1]};
                *(float2*)(C + (size_t)(n0 + m) * OUT + 2 * lane) = o;
            } else {
                float4 o = {acc[m][0], acc[m][1], acc[m][2], acc[m][3]};
                *(float4*)(C + (size_t)(n0 + m) * OUT + 4 * lane) = o;
            }
        }
    }
}

__global__ void k_gemm1(const float* __restrict__ x, const float* __restrict__ W1) {
    gemm_tiled<IND, HID, false>(x, W1, nullptr, g_h1);
}
// gemm2 + bias + relu + global mean-pool accumulate (no h2 materialization)
__global__ void k_gemm2pool(const float* __restrict__ W2, const float* __restrict__ b2) {
    gemm_tiled<HID, EMB, true>(g_agg2, W2, b2, nullptr);
}

// ---------------- CSR aggregation over 64-dim rows, warp per dst node -------
// O[i,:] = f( dis[i]^2 * H[i,:] + sum_e coef[e]*H[src[e],:] )
template <bool RELU>
__device__ __forceinline__ void agg_body(const float* __restrict__ H,
                                         const float* __restrict__ bias,
                                         float* __restrict__ O) {
    int node = (blockIdx.x * blockDim.x + threadIdx.x) >> 5;
    int lane = threadIdx.x & 31;
    if (node >= NN) return;

    const float2* __restrict__ H2 = (const float2*)H;
    int start = g_rowptr[node];
    int end = g_rowptr[node + 1];

    float s = g_dis[node];
    s *= s;
    float2 h = H2[(size_t)node * 32 + lane];
    float2 acc = {s * h.x, s * h.y};

    int k = start;
    int n4 = start + ((end - start) & ~3);
    for (; k < n4; k += 4) {
        int s0 = g_es_src[k], s1 = g_es_src[k + 1];
        int s2 = g_es_src[k + 2], s3 = g_es_src[k + 3];
        float c0 = g_es_coef[k], c1 = g_es_coef[k + 1];
        float c2 = g_es_coef[k + 2], c3 = g_es_coef[k + 3];
        float2 h0 = H2[(size_t)s0 * 32 + lane];
        float2 h1 = H2[(size_t)s1 * 32 + lane];
        float2 h2 = H2[(size_t)s2 * 32 + lane];
        float2 h3 = H2[(size_t)s3 * 32 + lane];
        acc.x = fmaf(c0, h0.x, acc.x); acc.y = fmaf(c0, h0.y, acc.y);
        acc.x = fmaf(c1, h1.x, acc.x); acc.y = fmaf(c1, h1.y, acc.y);
        acc.x = fmaf(c2, h2.x, acc.x); acc.y = fmaf(c2, h2.y, acc.y);
        acc.x = fmaf(c3, h3.x, acc.x); acc.y = fmaf(c3, h3.y, acc.y);
    }
    for (; k < end; k++) {
        int si = g_es_src[k];
        float c = g_es_coef[k];
        float2 hh = H2[(size_t)si * 32 + lane];
        acc.x = fmaf(c, hh.x, acc.x);
        acc.y = fmaf(c, hh.y, acc.y);
    }

    if (RELU) {
        float2 b = ((const float2*)bias)[lane];
        acc.x = fmaxf(acc.x + b.x, 0.0f);
        acc.y = fmaxf(acc.y + b.y, 0.0f);
    }
    ((float2*)O)[(size_t)node * 32 + lane] = acc;
}

__global__ void k_agg1(const float* __restrict__ b1) {
    agg_body<true>(g_h1, b1, g_hr);          // g_hr = relu(A*g_h1 + b1)
}
__global__ void k_agg2() {
    agg_body<false>(g_hr, nullptr, g_agg2);  // g_agg2 = A*g_hr
}

// ---------------- mean divide ----------------
__global__ void k_div(float* __restrict__ out) {
    int gid = blockIdx.x * blockDim.x + threadIdx.x;
    if (gid < NG * EMB) out[gid] = g_pool[gid] / fmaxf(g_cnt[gid >> 7], 1.0f);
}

// ---------------- launch ----------------
extern "C" void kernel_launch(void* const* d_in, const int* in_sizes, int n_in,
                              void* d_out, int out_size) {
    const float* x     = (const float*)d_in[0];
    const void*  ei    = d_in[1];  // [2, NE] int32 or int64 — probed on device
    const float* ew    = (const float*)d_in[2];
    const void*  batch = d_in[3];
    const float* W1    = (const float*)d_in[4];
    const float* b1    = (const float*)d_in[5];
    const float* W2    = (const float*)d_in[6];
    const float* b2    = (const float*)d_in[7];
    float*       out   = (float*)d_out;

    const int T = 256;
    const int NBLK = (NN + 255) / 256;          // 196
    const int GBLK = ((NN + 3) / 4 + 7) / 8;    // gemm grid: 4 nodes/warp, 8 warps/blk

    k_detect<<<1, 32>>>(ei, batch);
    k_init<<<NBLK, T>>>();
    k_cvt_edge<<<(NE + T - 1) / T, T>>>(ei, ew);
    k_cvt_batch<<<NBLK, T>>>(batch);

    // CSR build
    k_scan1<<<NBLK, 256>>>();
    k_scan2<<<1, 256>>>(NBLK);
    k_scan3<<<NBLK, T>>>();
    k_scatter<<<(NE + T - 1) / T, T>>>(ew);

    // layer 1: h1 = x@W1 ; hr = relu(A*h1 + b1)
    k_gemm1<<<GBLK, T>>>(x, W1);
    k_agg1<<<(NN * 32 + T - 1) / T, T>>>(b1);

    // layer 2: agg2 = A*hr ; pool += relu(agg2@W2 + b2)  (fused epilogue)
    k_agg2<<<(NN * 32 + T - 1) / T, T>>>();
    k_gemm2pool<<<GBLK, T>>>(W2, b2);

    // mean
    k_div<<<(NG * EMB + T - 1) / T, T>>>(out);
}

// round 12
// speedup vs baseline: 2.3066x; 1.0801x over previous
#include <cuda_runtime.h>

#define NN 50000
#define NE 800000
#define NG 256
#define IND 128
#define HID 64
#define EMB 128

// ---------------- scratch (device globals; no allocation) ----------------
__device__ int g_src[NE];
__device__ int g_dst[NE];
__device__ int g_batch[NN];
__device__ int g_is64_edge;
__device__ int g_is64_batch;

__device__ int g_cntn[NN];       // edge count per dst node
__device__ int g_rowptr[NN + 1]; // CSR row pointers
__device__ int g_bsum[256];      // scan block sums
__device__ int g_boff[256];      // scan block offsets
__device__ int g_cursor[NN];     // scatter cursors

struct __align__(8) Edge { int s; float c; };
__device__ Edge g_es[NE];        // dst-sorted (src, coef) pairs

__device__ float g_deg[NN];
__device__ float g_dis[NN];
__device__ alignas(16) float g_h1[(size_t)NN * HID];    // x @ W1
__device__ alignas(16) float g_hr[(size_t)NN * HID];    // relu(A*h1 + b1)
__device__ alignas(16) float g_agg2[(size_t)NN * HID];  // A * hr
__device__ alignas(16) float g_pool[NG * EMB];
__device__ float g_cnt[NG];

// vector f32 reduction (sm_90+)
__device__ __forceinline__ void red_add_v4(float* p, float a, float b, float c, float d) {
    asm volatile("red.global.add.v4.f32 [%0], {%1,%2,%3,%4};"
                 :: "l"(p), "f"(a), "f"(b), "f"(c), "f"(d) : "memory");
}

// ---------------- dtype probe (parallel) ----------------
__global__ void k_detect(const void* ei, const void* batch) {
    __shared__ int se, sb;
    if (threadIdx.x == 0) { se = 1; sb = 1; }
    __syncthreads();
    int t = threadIdx.x;  // 1024 threads
    if (((const int*)ei)[2 * t + 1] != 0) se = 0;
    if (((const int*)batch)[2 * t + 1] != 0) sb = 0;
    __syncthreads();
    if (t == 0) { g_is64_edge = se; g_is64_batch = sb; }
}

// ---------------- init: deg=1 (self loop), counters/pool = 0 ----------------
__global__ void k_init() {
    int i = blockIdx.x * blockDim.x + threadIdx.x;
    if (i < NN) {
        g_deg[i] = 1.0f;
        g_cntn[i] = 0;
    }
    if (i < NG * EMB) g_pool[i] = 0.0f;
    if (i < NG) g_cnt[i] = 0.0f;
}

// convert edges + histogram (count per dst) + weighted degree, one pass
__global__ void k_cvt_edge(const void* ei, const float* __restrict__ ew) {
    int e = blockIdx.x * blockDim.x + threadIdx.x;
    if (e >= NE) return;
    int s, d;
    if (g_is64_edge) {
        const long long* p = (const long long*)ei;
        s = (int)p[e];
        d = (int)p[NE + e];
    } else {
        const int* p = (const int*)ei;
        s = p[e];
        d = p[NE + e];
    }
    g_src[e] = s;
    g_dst[e] = d;
    atomicAdd(&g_cntn[d], 1);
    atomicAdd(&g_deg[d], ew[e]);
}

// convert batch + per-graph node count (warp-aggregated atomics)
__global__ void k_cvt_batch(const void* batch) {
    int i = blockIdx.x * blockDim.x + threadIdx.x;
    if (i >= NN) return;
    int b;
    if (g_is64_batch) b = (int)((const long long*)batch)[i];
    else              b = ((const int*)batch)[i];
    g_batch[i] = b;
    unsigned mask = __match_any_sync(__activemask(), b);
    int leader = __ffs(mask) - 1;
    if ((threadIdx.x & 31) == leader)
        atomicAdd(&g_cnt[b], (float)__popc(mask));
}

// ---------------- 3-pass exclusive scan of g_cntn -> g_rowptr ----------------
__global__ void k_scan1() {
    __shared__ int sm[256];
    int t = threadIdx.x;
    int i = blockIdx.x * 256 + t;
    int v = (i < NN) ? g_cntn[i] : 0;
    sm[t] = v;
    __syncthreads();
#pragma unroll
    for (int off = 1; off < 256; off <<= 1) {
        int add = (t >= off) ? sm[t - off] : 0;
        __syncthreads();
        sm[t] += add;
        __syncthreads();
    }
    if (i < NN) g_rowptr[i] = sm[t] - v;  // exclusive
    if (t == 255) g_bsum[blockIdx.x] = sm[255];
}

__global__ void k_scan2(int nblk) {
    __shared__ int sm[256];
    int t = threadIdx.x;
    int v = (t < nblk) ? g_bsum[t] : 0;
    sm[t] = v;
    __syncthreads();
#pragma unroll
    for (int off = 1; off < 256; off <<= 1) {
        int add = (t >= off) ? sm[t - off] : 0;
        __syncthreads();
        sm[t] += add;
        __syncthreads();
    }
    if (t < nblk) g_boff[t] = sm[t] - v;  // exclusive
    if (t == 0) g_rowptr[NN] = NE;
}

// finalize rowptr/cursor + dis = rsqrt(deg) (fused)
__global__ void k_scan3() {
    int i = blockIdx.x * blockDim.x + threadIdx.x;
    if (i < NN) {
        int r = g_rowptr[i] + g_boff[i >> 8];
        g_rowptr[i] = r;
        g_cursor[i] = r;
        float d = g_deg[i];
        g_dis[i] = d > 0.0f ? rsqrtf(d) : 0.0f;
    }
}

// scatter edges into dst-sorted order with precomputed coefficient (one ST.64)
__global__ void k_scatter(const float* __restrict__ ew) {
    int e = blockIdx.x * blockDim.x + threadIdx.x;
    if (e >= NE) return;
    int s = g_src[e];
    int d = g_dst[e];
    int pos = atomicAdd(&g_cursor[d], 1);
    Edge out;
    out.s = s;
    out.c = g_dis[s] * ew[e] * g_dis[d];
    g_es[pos] = out;
}

// ---------------- f32x2 register-tiled GEMM ---------------------------------
// C[n, OUT] = A[n, IN] @ W[IN, OUT].
// kk-pairing: u64 accumulator holds (even-k, odd-k) partial sums; operands are
// natural LDS.64 pairs: xs[m][2t..2t+1] and transposed Wst[col][2t..2t+1].
// Lane owns interleaved cols {lane, lane+32, ...} (conflict-free Wst loads).
// POOLFUSE: regroup cols via smem staging, relu(+bias), v4-RED into g_pool.
template <int IN, int OUT, bool POOLFUSE>
__device__ __forceinline__ void gemm_f32x2(const float* __restrict__ A,
                                           const float* __restrict__ W,
                                           const float* __restrict__ bias,
                                           float* __restrict__ C) {
    constexpr int MT = 8;
    constexpr int VEC = OUT / 32;     // 2 (OUT=64) or 4 (OUT=128)
    constexpr int INP = IN + 2;       // pad: 2-phase-safe LDS.64 banks
    constexpr int KB = 32;
    __shared__ __align__(16) float Wst[OUT * INP];   // W transposed [col][k]
    __shared__ __align__(16) float xs[8][MT][KB];
    __shared__ __align__(16) float stg[8][POOLFUSE ? EMB : 4];

    for (int i = threadIdx.x; i < IN * OUT; i += blockDim.x) {
        int k = i / OUT, c = i % OUT;
        Wst[c * INP + k] = W[i];
    }
    __syncthreads();

    const int warp = threadIdx.x >> 5;
    const int lane = threadIdx.x & 31;
    const int n0 = (blockIdx.x * 8 + warp) * MT;
    if (n0 >= NN) return;

    unsigned long long acc[MT][VEC];
#pragma unroll
    for (int m = 0; m < MT; m++)
#pragma unroll
        for (int c = 0; c < VEC; c++) acc[m][c] = 0ULL;

    for (int kb = 0; kb < IN; kb += KB) {
#pragma unroll
        for (int m = 0; m < MT; m++)
            xs[warp][m][lane] = (n0 + m < NN) ? A[(size_t)(n0 + m) * IN + kb + lane] : 0.0f;
        __syncwarp();
#pragma unroll
        for (int t = 0; t < KB / 2; t++) {
            unsigned long long xp[MT];
#pragma unroll
            for (int m = 0; m < MT; m++)
                xp[m] = *(const unsigned long long*)&xs[warp][m][2 * t];
            unsigned long long wp[VEC];
#pragma unroll
            for (int c = 0; c < VEC; c++)
                wp[c] = *(const unsigned long long*)&Wst[(lane + 32 * c) * INP + kb + 2 * t];
#pragma unroll
            for (int m = 0; m < MT; m++)
#pragma unroll
                for (int c = 0; c < VEC; c++)
                    asm("fma.rn.f32x2 %0, %1, %2, %0;"
                        : "+l"(acc[m][c]) : "l"(xp[m]), "l"(wp[c]));
        }
        __syncwarp();
    }

#pragma unroll
    for (int m = 0; m < MT; m++) {
        int n = n0 + m;
        if (n >= NN) break;  // uniform across warp
        float val[VEC];
#pragma unroll
        for (int c = 0; c < VEC; c++) {
            float lo = __uint_as_float((unsigned)acc[m][c]);
            float hi = __uint_as_float((unsigned)(acc[m][c] >> 32));
            val[c] = lo + hi;
        }
        if (!POOLFUSE) {
#pragma unroll
            for (int c = 0; c < VEC; c++)
                C[(size_t)n * OUT + lane + 32 * c] = val[c];
        } else {
#pragma unroll
            for (int c = 0; c < VEC; c++) stg[warp][lane + 32 * c] = val[c];
            __syncwarp();
            float4 v = *(const float4*)&stg[warp][4 * lane];
            float4 b = ((const float4*)bias)[lane];
            v.x = fmaxf(v.x + b.x, 0.0f);
            v.y = fmaxf(v.y + b.y, 0.0f);
            v.z = fmaxf(v.z + b.z, 0.0f);
            v.w = fmaxf(v.w + b.w, 0.0f);
            int g = g_batch[n];
            red_add_v4(g_pool + g * EMB + 4 * lane, v.x, v.y, v.z, v.w);
            __syncwarp();
        }
    }
}

__global__ void __launch_bounds__(256) k_gemm1(const float* __restrict__ x,
                                               const float* __restrict__ W1) {
    gemm_f32x2<IND, HID, false>(x, W1, nullptr, g_h1);
}
// gemm2 + bias + relu + global mean-pool accumulate (no h2 materialization)
__global__ void __launch_bounds__(256) k_gemm2pool(const float* __restrict__ W2,
                                                   const float* __restrict__ b2) {
    gemm_f32x2<HID, EMB, true>(g_agg2, W2, b2, nullptr);
}

// ---------------- CSR aggregation over 64-dim rows, warp per dst node -------
// O[i,:] = f( dis[i]^2 * H[i,:] + sum_e coef[e]*H[src[e],:] )
template <bool RELU>
__device__ __forceinline__ void agg_body(const float* __restrict__ H,
                                         const float* __restrict__ bias,
                                         float* __restrict__ O) {
    int node = (blockIdx.x * blockDim.x + threadIdx.x) >> 5;
    int lane = threadIdx.x & 31;
    if (node >= NN) return;

    const float2* __restrict__ H2 = (const float2*)H;
    int start = g_rowptr[node];
    int end = g_rowptr[node + 1];

    float s = g_dis[node];
    s *= s;
    float2 h = H2[(size_t)node * 32 + lane];
    float2 acc = {s * h.x, s * h.y};

    int k = start;
    int n4 = start + ((end - start) & ~3);
    for (; k < n4; k += 4) {
        Edge e0 = g_es[k], e1 = g_es[k + 1], e2 = g_es[k + 2], e3 = g_es[k + 3];
        float2 h0 = H2[(size_t)e0.s * 32 + lane];
        float2 h1 = H2[(size_t)e1.s * 32 + lane];
        float2 h2 = H2[(size_t)e2.s * 32 + lane];
        float2 h3 = H2[(size_t)e3.s * 32 + lane];
        acc.x = fmaf(e0.c, h0.x, acc.x); acc.y = fmaf(e0.c, h0.y, acc.y);
        acc.x = fmaf(e1.c, h1.x, acc.x); acc.y = fmaf(e1.c, h1.y, acc.y);
        acc.x = fmaf(e2.c, h2.x, acc.x); acc.y = fmaf(e2.c, h2.y, acc.y);
        acc.x = fmaf(e3.c, h3.x, acc.x); acc.y = fmaf(e3.c, h3.y, acc.y);
    }
    for (; k < end; k++) {
        Edge e = g_es[k];
        float2 hh = H2[(size_t)e.s * 32 + lane];
        acc.x = fmaf(e.c, hh.x, acc.x);
        acc.y = fmaf(e.c, hh.y, acc.y);
    }

    if (RELU) {
        float2 b = ((const float2*)bias)[lane];
        acc.x = fmaxf(acc.x + b.x, 0.0f);
        acc.y = fmaxf(acc.y + b.y, 0.0f);
    }
    ((float2*)O)[(size_t)node * 32 + lane] = acc;
}

__global__ void k_agg1(const float* __restrict__ b1) {
    agg_body<true>(g_h1, b1, g_hr);          // g_hr = relu(A*g_h1 + b1)
}
__global__ void k_agg2() {
    agg_body<false>(g_hr, nullptr, g_agg2);  // g_agg2 = A*g_hr
}

// ---------------- mean divide ----------------
__global__ void k_div(float* __restrict__ out) {
    int gid = blockIdx.x * blockDim.x + threadIdx.x;
    if (gid < NG * EMB) out[gid] = g_pool[gid] / fmaxf(g_cnt[gid >> 7], 1.0f);
}

// ---------------- launch ----------------
extern "C" void kernel_launch(void* const* d_in, const int* in_sizes, int n_in,
                              void* d_out, int out_size) {
    const float* x     = (const float*)d_in[0];
    const void*  ei    = d_in[1];  // [2, NE] int32 or int64 — probed on device
    const float* ew    = (const float*)d_in[2];
    const void*  batch = d_in[3];
    const float* W1    = (const float*)d_in[4];
    const float* b1    = (const float*)d_in[5];
    const float* W2    = (const float*)d_in[6];
    const float* b2    = (const float*)d_in[7];
    float*       out   = (float*)d_out;

    const int T = 256;
    const int NBLK = (NN + 255) / 256;            // 196
    const int GBLK = (NN + 63) / 64;              // 8 nodes/warp * 8 warps

    k_detect<<<1, 1024>>>(ei, batch);
    k_init<<<NBLK, T>>>();
    k_cvt_edge<<<(NE + T - 1) / T, T>>>(ei, ew);
    k_cvt_batch<<<NBLK, T>>>(batch);

    // CSR build
    k_scan1<<<NBLK, 256>>>();
    k_scan2<<<1, 256>>>(NBLK);
    k_scan3<<<NBLK, T>>>();
    k_scatter<<<(NE + T - 1) / T, T>>>(ew);

    // layer 1: h1 = x@W1 ; hr = relu(A*h1 + b1)
    k_gemm1<<<GBLK, T>>>(x, W1);
    k_agg1<<<(NN * 32 + T - 1) / T, T>>>(b1);

    // layer 2: agg2 = A*hr ; pool += relu(agg2@W2 + b2)  (fused epilogue)
    k_agg2<<<(NN * 32 + T - 1) / T, T>>>();
    k_gemm2pool<<<GBLK, T>>>(W2, b2);

    // mean
    k_div<<<(NG * EMB + T - 1) / T, T>>>(out);
}

// round 13
// speedup vs baseline: 2.4759x; 1.0734x over previous
#include <cuda_runtime.h>
#include <cuda_fp16.h>

#define NN 50000
#define NE 800000
#define NG 256
#define IND 128
#define HID 64
#define EMB 128

// ---------------- scratch (device globals; no allocation) ----------------
__device__ int g_src[NE];
__device__ int g_dst[NE];
__device__ int g_batch[NN];
__device__ int g_is64_edge;
__device__ int g_is64_batch;

__device__ int g_cntn[NN];       // edge count per dst node
__device__ int g_rowptr[NN + 1]; // CSR row pointers
__device__ int g_bsum[256];      // scan block sums
__device__ int g_boff[256];      // scan block offsets
__device__ int g_cursor[NN];     // scatter cursors

struct __align__(8) Edge { int s; float c; };
__device__ Edge g_es[NE];        // dst-sorted (src, coef) pairs

__device__ float g_deg[NN];
__device__ float g_dis[NN];
// h stored as half2 (col pairs 2l,2l+1): halves gather traffic; math stays fp32
__device__ alignas(16) __half2 g_h1h[(size_t)NN * 32];  // x @ W1 (half storage)
__device__ alignas(16) __half2 g_hrh[(size_t)NN * 32];  // relu(A*h1 + b1)
__device__ alignas(16) float g_agg2[(size_t)NN * HID];  // A * hr (fp32 for gemm2)
__device__ alignas(16) float g_pool[NG * EMB];
__device__ float g_cnt[NG];

// vector f32 reduction (sm_90+)
__device__ __forceinline__ void red_add_v4(float* p, float a, float b, float c, float d) {
    asm volatile("red.global.add.v4.f32 [%0], {%1,%2,%3,%4};"
                 :: "l"(p), "f"(a), "f"(b), "f"(c), "f"(d) : "memory");
}

// ---------------- dtype probe (parallel) ----------------
__global__ void k_detect(const void* ei, const void* batch) {
    __shared__ int se, sb;
    if (threadIdx.x == 0) { se = 1; sb = 1; }
    __syncthreads();
    int t = threadIdx.x;  // 1024 threads
    if (((const int*)ei)[2 * t + 1] != 0) se = 0;
    if (((const int*)batch)[2 * t + 1] != 0) sb = 0;
    __syncthreads();
    if (t == 0) { g_is64_edge = se; g_is64_batch = sb; }
}

// ---------------- init: deg=1 (self loop), counters/pool = 0 ----------------
__global__ void k_init() {
    int i = blockIdx.x * blockDim.x + threadIdx.x;
    if (i < NN) {
        g_deg[i] = 1.0f;
        g_cntn[i] = 0;
    }
    if (i < NG * EMB) g_pool[i] = 0.0f;
    if (i < NG) g_cnt[i] = 0.0f;
}

// convert edges + histogram (count per dst) + weighted degree, one pass
__global__ void k_cvt_edge(const void* ei, const float* __restrict__ ew) {
    int e = blockIdx.x * blockDim.x + threadIdx.x;
    if (e >= NE) return;
    int s, d;
    if (g_is64_edge) {
        const long long* p = (const long long*)ei;
        s = (int)p[e];
        d = (int)p[NE + e];
    } else {
        const int* p = (const int*)ei;
        s = p[e];
        d = p[NE + e];
    }
    g_src[e] = s;
    g_dst[e] = d;
    atomicAdd(&g_cntn[d], 1);
    atomicAdd(&g_deg[d], ew[e]);
}

// convert batch + per-graph node count (warp-aggregated atomics)
__global__ void k_cvt_batch(const void* batch) {
    int i = blockIdx.x * blockDim.x + threadIdx.x;
    if (i >= NN) return;
    int b;
    if (g_is64_batch) b = (int)((const long long*)batch)[i];
    else              b = ((const int*)batch)[i];
    g_batch[i] = b;
    unsigned mask = __match_any_sync(__activemask(), b);
    int leader = __ffs(mask) - 1;
    if ((threadIdx.x & 31) == leader)
        atomicAdd(&g_cnt[b], (float)__popc(mask));
}

// ---------------- 3-pass exclusive scan of g_cntn -> g_rowptr ----------------
__global__ void k_scan1() {
    __shared__ int sm[256];
    int t = threadIdx.x;
    int i = blockIdx.x * 256 + t;
    int v = (i < NN) ? g_cntn[i] : 0;
    sm[t] = v;
    __syncthreads();
#pragma unroll
    for (int off = 1; off < 256; off <<= 1) {
        int add = (t >= off) ? sm[t - off] : 0;
        __syncthreads();
        sm[t] += add;
        __syncthreads();
    }
    if (i < NN) g_rowptr[i] = sm[t] - v;  // exclusive
    if (t == 255) g_bsum[blockIdx.x] = sm[255];
}

__global__ void k_scan2(int nblk) {
    __shared__ int sm[256];
    int t = threadIdx.x;
    int v = (t < nblk) ? g_bsum[t] : 0;
    sm[t] = v;
    __syncthreads();
#pragma unroll
    for (int off = 1; off < 256; off <<= 1) {
        int add = (t >= off) ? sm[t - off] : 0;
        __syncthreads();
        sm[t] += add;
        __syncthreads();
    }
    if (t < nblk) g_boff[t] = sm[t] - v;  // exclusive
    if (t == 0) g_rowptr[NN] = NE;
}

// finalize rowptr/cursor + dis = rsqrt(deg) (fused)
__global__ void k_scan3() {
    int i = blockIdx.x * blockDim.x + threadIdx.x;
    if (i < NN) {
        int r = g_rowptr[i] + g_boff[i >> 8];
        g_rowptr[i] = r;
        g_cursor[i] = r;
        float d = g_deg[i];
        g_dis[i] = d > 0.0f ? rsqrtf(d) : 0.0f;
    }
}

// scatter edges into dst-sorted order with precomputed coefficient (one ST.64)
__global__ void k_scatter(const float* __restrict__ ew) {
    int e = blockIdx.x * blockDim.x + threadIdx.x;
    if (e >= NE) return;
    int s = g_src[e];
    int d = g_dst[e];
    int pos = atomicAdd(&g_cursor[d], 1);
    Edge out;
    out.s = s;
    out.c = g_dis[s] * ew[e] * g_dis[d];
    g_es[pos] = out;
}

// ---------------- f32x2 register-tiled GEMM ---------------------------------
// C = A @ W. kk-paired u64 accumulators; LDS.64 operands (xs pairs + transposed
// Wst pairs); lane owns interleaved cols {lane, lane+32, ...}.
// EPI=1: regroup cols via smem, convert to half2, store to g_h1h.
// EPI=2: regroup cols via smem, relu(+bias), v4-RED into g_pool (mean pool).
template <int IN, int OUT, int EPI>
__device__ __forceinline__ void gemm_f32x2(const float* __restrict__ A,
                                           const float* __restrict__ W,
                                           const float* __restrict__ bias) {
    constexpr int MT = 8;
    constexpr int VEC = OUT / 32;     // 2 (OUT=64) or 4 (OUT=128)
    constexpr int INP = IN + 2;       // pad: 2-phase-safe LDS.64 banks
    constexpr int KB = 32;
    __shared__ __align__(16) float Wst[OUT * INP];   // W transposed [col][k]
    __shared__ __align__(16) float xs[8][MT][KB];
    __shared__ __align__(16) float stg[8][OUT];

    for (int i = threadIdx.x; i < IN * OUT; i += blockDim.x) {
        int k = i / OUT, c = i % OUT;
        Wst[c * INP + k] = W[i];
    }
    __syncthreads();

    const int warp = threadIdx.x >> 5;
    const int lane = threadIdx.x & 31;
    const int n0 = (blockIdx.x * 8 + warp) * MT;
    if (n0 >= NN) return;

    unsigned long long acc[MT][VEC];
#pragma unroll
    for (int m = 0; m < MT; m++)
#pragma unroll
        for (int c = 0; c < VEC; c++) acc[m][c] = 0ULL;

    for (int kb = 0; kb < IN; kb += KB) {
#pragma unroll
        for (int m = 0; m < MT; m++)
            xs[warp][m][lane] = (n0 + m < NN) ? A[(size_t)(n0 + m) * IN + kb + lane] : 0.0f;
        __syncwarp();
#pragma unroll
        for (int t = 0; t < KB / 2; t++) {
            unsigned long long xp[MT];
#pragma unroll
            for (int m = 0; m < MT; m++)
                xp[m] = *(const unsigned long long*)&xs[warp][m][2 * t];
            unsigned long long wp[VEC];
#pragma unroll
            for (int c = 0; c < VEC; c++)
                wp[c] = *(const unsigned long long*)&Wst[(lane + 32 * c) * INP + kb + 2 * t];
#pragma unroll
            for (int m = 0; m < MT; m++)
#pragma unroll
                for (int c = 0; c < VEC; c++)
                    asm("fma.rn.f32x2 %0, %1, %2, %0;"
                        : "+l"(acc[m][c]) : "l"(xp[m]), "l"(wp[c]));
        }
        __syncwarp();
    }

#pragma unroll
    for (int m = 0; m < MT; m++) {
        int n = n0 + m;
        if (n >= NN) break;  // uniform across warp
        float val[VEC];
#pragma unroll
        for (int c = 0; c < VEC; c++) {
            float lo = __uint_as_float((unsigned)acc[m][c]);
            float hi = __uint_as_float((unsigned)(acc[m][c] >> 32));
            val[c] = lo + hi;
        }
#pragma unroll
        for (int c = 0; c < VEC; c++) stg[warp][lane + 32 * c] = val[c];
        __syncwarp();
        if (EPI == 1) {
            float2 v = *(const float2*)&stg[warp][2 * lane];  // cols 2l, 2l+1
            g_h1h[(size_t)n * 32 + lane] = __float22half2_rn(v);
        } else {
            float4 v = *(const float4*)&stg[warp][4 * lane];
            float4 b = ((const float4*)bias)[lane];
            v.x = fmaxf(v.x + b.x, 0.0f);
            v.y = fmaxf(v.y + b.y, 0.0f);
            v.z = fmaxf(v.z + b.z, 0.0f);
            v.w = fmaxf(v.w + b.w, 0.0f);
            int g = g_batch[n];
            red_add_v4(g_pool + g * EMB + 4 * lane, v.x, v.y, v.z, v.w);
        }
        __syncwarp();
    }
}

__global__ void __launch_bounds__(256) k_gemm1(const float* __restrict__ x,
                                               const float* __restrict__ W1) {
    gemm_f32x2<IND, HID, 1>(x, W1, nullptr);
}
// gemm2 + bias + relu + global mean-pool accumulate (no h2 materialization)
__global__ void __launch_bounds__(256) k_gemm2pool(const float* __restrict__ W2,
                                                   const float* __restrict__ b2) {
    gemm_f32x2<HID, EMB, 2>(g_agg2, W2, b2);
}

// ---------------- CSR aggregation, warp per dst node, half2 gathers ---------
// out[i,:] = f( dis[i]^2 * H[i,:] + sum_e coef[e]*H[src[e],:] ), fp32 math.
// OUTHALF: write half2 to g_hrh (with bias+relu); else fp32 float2 to g_agg2.
template <bool OUTHALF>
__device__ __forceinline__ void agg_body(const __half2* __restrict__ H,
                                         const float* __restrict__ bias) {
    int node = (blockIdx.x * blockDim.x + threadIdx.x) >> 5;
    int lane = threadIdx.x & 31;
    if (node >= NN) return;

    int start = g_rowptr[node];
    int end = g_rowptr[node + 1];

    float s = g_dis[node];
    s *= s;
    float2 h = __half22float2(H[(size_t)node * 32 + lane]);
    float2 acc = {s * h.x, s * h.y};

    int k = start;
    int n4 = start + ((end - start) & ~3);
    for (; k < n4; k += 4) {
        Edge e0 = g_es[k], e1 = g_es[k + 1], e2 = g_es[k + 2], e3 = g_es[k + 3];
        float2 h0 = __half22float2(H[(size_t)e0.s * 32 + lane]);
        float2 h1 = __half22float2(H[(size_t)e1.s * 32 + lane]);
        float2 h2 = __half22float2(H[(size_t)e2.s * 32 + lane]);
        float2 h3 = __half22float2(H[(size_t)e3.s * 32 + lane]);
        acc.x = fmaf(e0.c, h0.x, acc.x); acc.y = fmaf(e0.c, h0.y, acc.y);
        acc.x = fmaf(e1.c, h1.x, acc.x); acc.y = fmaf(e1.c, h1.y, acc.y);
        acc.x = fmaf(e2.c, h2.x, acc.x); acc.y = fmaf(e2.c, h2.y, acc.y);
        acc.x = fmaf(e3.c, h3.x, acc.x); acc.y = fmaf(e3.c, h3.y, acc.y);
    }
    for (; k < end; k++) {
        Edge e = g_es[k];
        float2 hh = __half22float2(H[(size_t)e.s * 32 + lane]);
        acc.x = fmaf(e.c, hh.x, acc.x);
        acc.y = fmaf(e.c, hh.y, acc.y);
    }

    if (OUTHALF) {
        float2 b = ((const float2*)bias)[lane];  // cols 2l, 2l+1
        acc.x = fmaxf(acc.x + b.x, 0.0f);
        acc.y = fmaxf(acc.y + b.y, 0.0f);
        g_hrh[(size_t)node * 32 + lane] = __float22half2_rn(acc);
    } else {
        ((float2*)g_agg2)[(size_t)node * 32 + lane] = acc;
    }
}

__global__ void k_agg1(const float* __restrict__ b1) {
    agg_body<true>(g_h1h, b1);     // g_hrh = half(relu(A*h1 + b1))
}
__global__ void k_agg2() {
    agg_body<false>(g_hrh, nullptr);  // g_agg2 = A*hr (fp32)
}

// ---------------- mean divide ----------------
__global__ void k_div(float* __restrict__ out) {
    int gid = blockIdx.x * blockDim.x + threadIdx.x;
    if (gid < NG * EMB) out[gid] = g_pool[gid] / fmaxf(g_cnt[gid >> 7], 1.0f);
}

// ---------------- launch ----------------
extern "C" void kernel_launch(void* const* d_in, const int* in_sizes, int n_in,
                              void* d_out, int out_size) {
    const float* x     = (const float*)d_in[0];
    const void*  ei    = d_in[1];  // [2, NE] int32 or int64 — probed on device
    const float* ew    = (const float*)d_in[2];
    const void*  batch = d_in[3];
    const float* W1    = (const float*)d_in[4];
    const float* b1    = (const float*)d_in[5];
    const float* W2    = (const float*)d_in[6];
    const float* b2    = (const float*)d_in[7];
    float*       out   = (float*)d_out;

    const int T = 256;
    const int NBLK = (NN + 255) / 256;            // 196
    const int GBLK = (NN + 63) / 64;              // 8 nodes/warp * 8 warps

    k_detect<<<1, 1024>>>(ei, batch);
    k_init<<<NBLK, T>>>();
    k_cvt_edge<<<(NE + T - 1) / T, T>>>(ei, ew);
    k_cvt_batch<<<NBLK, T>>>(batch);

    // CSR build
    k_scan1<<<NBLK, 256>>>();
    k_scan2<<<1, 256>>>(NBLK);
    k_scan3<<<NBLK, T>>>();
    k_scatter<<<(NE + T - 1) / T, T>>>(ew);

    // layer 1: h1 = half(x@W1) ; hr = half(relu(A*h1 + b1))
    k_gemm1<<<GBLK, T>>>(x, W1);
    k_agg1<<<(NN * 32 + T - 1) / T, T>>>(b1);

    // layer 2: agg2 = A*hr (fp32) ; pool += relu(agg2@W2 + b2)
    k_agg2<<<(NN * 32 + T - 1) / T, T>>>();
    k_gemm2pool<<<GBLK, T>>>(W2, b2);

    // mean
    k_div<<<(NG * EMB + T - 1) / T, T>>>(out);
}